// round 10
// baseline (speedup 1.0000x reference)
#include <cuda_runtime.h>
#include <cuda_fp16.h>
#include <math_constants.h>
#include <cstdint>

constexpr int B = 32, N = 2000, NPAD = 2048, D = 25088;
constexpr int ITOT = D / 64;     // 392 k-iters (dots)
constexpr int KC   = 18;         // dots k-chunks
constexpr int RIT  = NPAD / 64;  // 32 n-iters (read)

constexpr float EPS = 1e-8f, PI_2C = 3.14159f * 0.5f;

__device__ float  g_part[KC * B * NPAD];
__device__ float  g_msq [KC * NPAD];
__device__ uint4  g_kb  [ITOT * 4 * 32 * 2];  // key prepacked in mma-fragment order
__device__ float  g_kn  [B];
__device__ float  g_sum [B];
__device__ float  g_ev  [B * NPAD];
__device__ __half g_whi [B * NPAD];           // padding [2000,2048) stays 0

__device__ __forceinline__ uint32_t smem_u32(const void* p) {
    uint32_t a;
    asm("{ .reg .u64 t; cvta.to.shared.u64 t, %1; cvt.u32.u64 %0, t; }" : "=r"(a) : "l"(p));
    return a;
}
__device__ __forceinline__ void ldm4(uint32_t& r0, uint32_t& r1, uint32_t& r2, uint32_t& r3, uint32_t a) {
    asm volatile("ldmatrix.sync.aligned.m8n8.x4.shared.b16 {%0,%1,%2,%3}, [%4];"
                 : "=r"(r0), "=r"(r1), "=r"(r2), "=r"(r3) : "r"(a));
}
__device__ __forceinline__ void ldm4t(uint32_t& r0, uint32_t& r1, uint32_t& r2, uint32_t& r3, uint32_t a) {
    asm volatile("ldmatrix.sync.aligned.m8n8.x4.trans.shared.b16 {%0,%1,%2,%3}, [%4];"
                 : "=r"(r0), "=r"(r1), "=r"(r2), "=r"(r3) : "r"(a));
}
__device__ __forceinline__ void mma_h(float* c, uint32_t a0, uint32_t a1, uint32_t a2, uint32_t a3,
                                      uint32_t b0, uint32_t b1) {
    asm volatile("mma.sync.aligned.m16n8k16.row.col.f32.f16.f16.f32 "
                 "{%0,%1,%2,%3}, {%4,%5,%6,%7}, {%8,%9}, {%0,%1,%2,%3};"
                 : "+f"(c[0]), "+f"(c[1]), "+f"(c[2]), "+f"(c[3])
                 : "r"(a0), "r"(a1), "r"(a2), "r"(a3), "r"(b0), "r"(b1));
}
__device__ __forceinline__ uint32_t h2(float a, float b) {
    __half2 h = __floats2half2_rn(a, b);
    return *(uint32_t*)&h;
}

// ---------------------------------------------------------------------------
// Kernel 0: prepack key -> dots B fragments. Grid 196 x 256. (proven)
// ---------------------------------------------------------------------------
__global__ __launch_bounds__(256) void prepack_kernel(const float* __restrict__ key)
{
    const int gid = blockIdx.x * 256 + threadIdx.x;
    const int t = gid & 31, s = gid >> 5;
    const int d = (s >> 2) * 64 + (s & 3) * 16 + 2 * (t & 3);
    uint32_t v0[4], v1[4];
    #pragma unroll
    for (int nf = 0; nf < 4; nf++) {
        const int row = (t >> 2) + 8 * nf;
        const float2 x0 = *(const float2*)&key[row * D + d];
        const float2 x1 = *(const float2*)&key[row * D + d + 8];
        v0[nf] = h2(x0.x, x0.y);
        v1[nf] = h2(x1.x, x1.y);
    }
    g_kb[(s * 32 + t) * 2    ] = make_uint4(v0[0], v0[1], v0[2], v0[3]);
    g_kb[(s * 32 + t) * 2 + 1] = make_uint4(v1[0], v1[1], v1[2], v1[3]);
}

// ---------------------------------------------------------------------------
// Kernel 1: dots^T partials + m-norm partials. (R7 verbatim — proven fastest)
// ---------------------------------------------------------------------------
__global__ __launch_bounds__(256) void dots_kernel(const float* __restrict__ mem)
{
    const int tid = threadIdx.x, w = tid >> 5, t = tid & 31;
    const int n0 = blockIdx.x * 128, kc = blockIdx.y;
    const int it0 = kc * ITOT / KC, it1 = (kc + 1) * ITOT / KC;
    const int nst = (it1 - it0) * 4;
    const int r0 = n0 + w * 16 + (t >> 2);
    const int qc = 2 * (t & 3);
    const bool ok0 = r0 < N, ok1 = (r0 + 8) < N;
    const float* q0 = mem + (long long)(ok0 ? r0 : 0) * D + it0 * 64 + qc;
    const float* q1 = mem + (long long)(ok1 ? r0 + 8 : 0) * D + it0 * 64 + qc;
    const uint4* kb = g_kb + ((long long)(it0 * 4) * 32 + t) * 2;

    float acc[4][4];
    #pragma unroll
    for (int f = 0; f < 4; f++)
        #pragma unroll
        for (int i = 0; i < 4; i++) acc[f][i] = 0.f;
    float ms0 = 0.f, ms1 = 0.f;

    float2 fa[2][4]; uint4 fb[2][2];
    fa[0][0] = *(const float2*)q0;
    fa[0][1] = *(const float2*)q1;
    fa[0][2] = *(const float2*)(q0 + 8);
    fa[0][3] = *(const float2*)(q1 + 8);
    fb[0][0] = kb[0];
    fb[0][1] = kb[1];

    for (int j = 0; j < nst; ++j) {
        const int b = j & 1;
        if (j + 1 < nst) {
            const float* a0 = q0 + (j + 1) * 16;
            const float* a1 = q1 + (j + 1) * 16;
            fa[b ^ 1][0] = *(const float2*)a0;
            fa[b ^ 1][1] = *(const float2*)a1;
            fa[b ^ 1][2] = *(const float2*)(a0 + 8);
            fa[b ^ 1][3] = *(const float2*)(a1 + 8);
            fb[b ^ 1][0] = kb[(j + 1) * 64];
            fb[b ^ 1][1] = kb[(j + 1) * 64 + 1];
        }
        float2 f0 = fa[b][0], f1 = fa[b][1], f2v = fa[b][2], f3 = fa[b][3];
        if (!ok0) { f0 = make_float2(0.f, 0.f); f2v = make_float2(0.f, 0.f); }
        if (!ok1) { f1 = make_float2(0.f, 0.f); f3 = make_float2(0.f, 0.f); }
        ms0 = fmaf(f0.x, f0.x, fmaf(f0.y, f0.y, ms0));
        ms0 = fmaf(f2v.x, f2v.x, fmaf(f2v.y, f2v.y, ms0));
        ms1 = fmaf(f1.x, f1.x, fmaf(f1.y, f1.y, ms1));
        ms1 = fmaf(f3.x, f3.x, fmaf(f3.y, f3.y, ms1));
        const uint32_t a0 = h2(f0.x, f0.y), a1 = h2(f1.x, f1.y);
        const uint32_t a2 = h2(f2v.x, f2v.y), a3 = h2(f3.x, f3.y);
        const uint4 B0 = fb[b][0], B1 = fb[b][1];
        mma_h(acc[0], a0, a1, a2, a3, B0.x, B1.x);
        mma_h(acc[1], a0, a1, a2, a3, B0.y, B1.y);
        mma_h(acc[2], a0, a1, a2, a3, B0.z, B1.z);
        mma_h(acc[3], a0, a1, a2, a3, B0.w, B1.w);
    }

    const int nrow = n0 + w * 16 + (t >> 2);
    #pragma unroll
    for (int nf = 0; nf < 4; nf++) {
        g_part[(kc * B + 8 * nf + qc    ) * NPAD + nrow    ] = acc[nf][0];
        g_part[(kc * B + 8 * nf + qc + 1) * NPAD + nrow    ] = acc[nf][1];
        g_part[(kc * B + 8 * nf + qc    ) * NPAD + nrow + 8] = acc[nf][2];
        g_part[(kc * B + 8 * nf + qc + 1) * NPAD + nrow + 8] = acc[nf][3];
    }
    ms0 += __shfl_xor_sync(0xffffffffu, ms0, 1);
    ms0 += __shfl_xor_sync(0xffffffffu, ms0, 2);
    ms1 += __shfl_xor_sync(0xffffffffu, ms1, 1);
    ms1 += __shfl_xor_sync(0xffffffffu, ms1, 2);
    if ((t & 3) == 0) {
        g_msq[kc * NPAD + n0 + w * 16 + (t >> 2)    ] = ms0;
        g_msq[kc * NPAD + n0 + w * 16 + (t >> 2) + 8] = ms1;
    }
}

// ---------------------------------------------------------------------------
// Kernel 2a: key norms + reset g_sum (R8 verbatim — proven). Grid 32 x 256.
// ---------------------------------------------------------------------------
__global__ __launch_bounds__(256) void keynorm_kernel(const float* __restrict__ key)
{
    const int b = blockIdx.x, tid = threadIdx.x;
    __shared__ float red[256];
    float s = 0.f;
    for (int i = tid; i < D; i += 256) { const float v = key[b * D + i]; s = fmaf(v, v, s); }
    red[tid] = s; __syncthreads();
    for (int o = 128; o > 0; o >>= 1) { if (tid < o) red[tid] += red[tid + o]; __syncthreads(); }
    if (tid == 0) {
        g_kn[b]  = fmaxf(sqrtf(red[0]), EPS);
        g_sum[b] = 0.f;
    }
}

// ---------------------------------------------------------------------------
// Kernel 2b: reduce partials + cos -> tan -> exp (shift-free; proven in R8 to
// match shifted version at this data scale). Grid (8, 32) x 256.
// ---------------------------------------------------------------------------
__global__ __launch_bounds__(256) void expsum_kernel()
{
    const int b = blockIdx.y, n = blockIdx.x * 256 + threadIdx.x, tid = threadIdx.x;
    __shared__ float red[256];
    float ev = 0.f;
    if (n < N) {
        float dot = 0.f, ms = 0.f;
        #pragma unroll
        for (int c = 0; c < KC; c++) {
            dot += g_part[(c * B + b) * NPAD + n];
            ms  += g_msq[c * NPAD + n];
        }
        const float mn = fmaxf(sqrtf(ms), EPS);
        ev = expf(tanf((dot / (g_kn[b] * mn)) * PI_2C));
        g_ev[b * NPAD + n] = ev;
    }
    red[tid] = ev; __syncthreads();
    for (int o = 128; o > 0; o >>= 1) { if (tid < o) red[tid] += red[tid + o]; __syncthreads(); }
    if (tid == 0) atomicAdd(&g_sum[b], red[0]);
}

// ---------------------------------------------------------------------------
// Kernel 2c: normalize -> single fp16 w. Grid (8, 32) x 256.
// ---------------------------------------------------------------------------
__global__ __launch_bounds__(256) void wsplit_kernel()
{
    const int b = blockIdx.y, n = blockIdx.x * 256 + threadIdx.x;
    if (n < N)
        g_whi[b * NPAD + n] = __float2half(g_ev[b * NPAD + n] / g_sum[b]);
}

// ---------------------------------------------------------------------------
// Kernel 3: out[b,d] = sum_n w[b,n] m[n,d]. Grid 392 (d-tile 64), 256 thr.
// Single-pass fp16 w: A = w [32 b][64 n]; B = m tile [64 n][64 d] fp16.
// 8 warps = 2 (m16 frag) x 4 (16-d slice). No epilogue reduce.
// smem: A 2x32x72 (9216B) + B 2x64x72 (18432B) = 27648 dyn.
// ---------------------------------------------------------------------------
__global__ __launch_bounds__(256) void read_kernel(
    const float* __restrict__ mem, float* __restrict__ out)
{
    extern __shared__ __align__(16) __half sm[];
    __half* Aw = sm;                    // [buf][32][72]
    __half* Bt = sm + 2 * 32 * 72;      // [buf][64][72]
    const uint32_t sbA = smem_u32(Aw), sbB = smem_u32(Bt);
    const int tid = threadIdx.x, w = tid >> 5, t = tid & 31;
    const int d0 = blockIdx.x * 64;
    const int mf = w >> 2, nj = w & 3;
    const int wr = tid >> 3, ch = tid & 7;   // A loads: b row 0..31, 16B chunk 0..7

    uint4 rA; float4 rB[4];
    {
        rA = *(const uint4*)&g_whi[wr * NPAD + ch * 8];
        #pragma unroll
        for (int p = 0; p < 4; p++) {
            const int idx = tid + 256 * p, row = idx >> 4, c4 = idx & 15;
            const int n = row < N ? row : 0;
            rB[p] = *(const float4*)&mem[(long long)n * D + d0 + c4 * 4];
        }
    }

    float acc[2][4];
    #pragma unroll
    for (int bf = 0; bf < 2; bf++)
        #pragma unroll
        for (int i = 0; i < 4; i++) acc[bf][i] = 0.f;

    for (int it = 0; it < RIT; ++it) {
        const int buf = it & 1;
        __half* A  = Aw + buf * 32 * 72;
        __half* Bm = Bt + buf * 64 * 72;
        *(uint4*)&A[wr * 72 + ch * 8] = rA;
        #pragma unroll
        for (int p = 0; p < 4; p++) {
            const int idx = tid + 256 * p, row = idx >> 4, c4 = idx & 15;
            *(uint2*)&Bm[row * 72 + c4 * 4] = make_uint2(h2(rB[p].x, rB[p].y), h2(rB[p].z, rB[p].w));
        }
        __syncthreads();
        if (it + 1 < RIT) {
            const int nb = (it + 1) * 64;
            rA = *(const uint4*)&g_whi[wr * NPAD + nb + ch * 8];
            #pragma unroll
            for (int p = 0; p < 4; p++) {
                const int idx = tid + 256 * p, row = idx >> 4, c4 = idx & 15;
                const int n = nb + row;
                const int nn = n < N ? n : 0;
                rB[p] = *(const float4*)&mem[(long long)nn * D + d0 + c4 * 4];
            }
        }
        const int lr = (t & 7) + 8 * ((t >> 3) & 1);
        const int lh = 8 * (t >> 4);
        #pragma unroll
        for (int kk = 0; kk < 4; kk++) {
            uint32_t a0, a1, a2, a3, bq[4];
            ldm4(a0, a1, a2, a3,
                 sbA + 2u * (buf * 32 * 72 + (mf * 16 + lr) * 72 + kk * 16 + lh));
            ldm4t(bq[0], bq[1], bq[2], bq[3],
                  sbB + 2u * (buf * 64 * 72 + (kk * 16 + lr) * 72 + nj * 16 + lh));
            mma_h(acc[0], a0, a1, a2, a3, bq[0], bq[1]);
            mma_h(acc[1], a0, a1, a2, a3, bq[2], bq[3]);
        }
        __syncthreads();
    }

    // epilogue: warp owns b rows {mf*16 + t/4, +8} x d cols nj*16..+15
    #pragma unroll
    for (int bf = 0; bf < 2; bf++) {
        const int b   = mf * 16 + (t >> 2);
        const int col = d0 + nj * 16 + bf * 8 + 2 * (t & 3);
        *(float2*)&out[b * D + col]       = make_float2(acc[bf][0], acc[bf][1]);
        *(float2*)&out[(b + 8) * D + col] = make_float2(acc[bf][2], acc[bf][3]);
    }
}

// ---------------------------------------------------------------------------
extern "C" void kernel_launch(void* const* d_in, const int* in_sizes, int n_in,
                              void* d_out, int out_size)
{
    const float* key = (const float*)d_in[0];
    const float* mem = (const float*)d_in[1];
    float* out = (float*)d_out;

    cudaFuncSetAttribute(read_kernel, cudaFuncAttributeMaxDynamicSharedMemorySize, 27648);

    prepack_kernel<<<ITOT * 4 * 32 / 256, 256>>>(key);
    dots_kernel<<<dim3(16, KC), 256>>>(mem);
    keynorm_kernel<<<32, 256>>>(key);
    expsum_kernel<<<dim3(8, 32), 256>>>();
    wsplit_kernel<<<dim3(8, 32), 256>>>();
    read_kernel<<<D / 64, 256, 27648>>>(mem, out);
}

// round 11
// speedup vs baseline: 1.2731x; 1.2731x over previous
#include <cuda_runtime.h>
#include <cuda_fp16.h>
#include <math_constants.h>
#include <cstdint>

constexpr int B = 32, N = 2000, NPAD = 2048, D = 25088;
constexpr int ITOT = D / 64;     // 392 k-iters (dots)
constexpr int KC   = 18;         // dots k-chunks
constexpr int RIT  = NPAD / 64;  // 32 n-iters (read)

constexpr float EPS = 1e-8f, PI_2C = 3.14159f * 0.5f;

__device__ float  g_part[KC * B * NPAD];
__device__ float  g_msq [KC * NPAD];
__device__ uint4  g_kb  [ITOT * 4 * 32 * 2];  // key prepacked in mma-fragment order
__device__ __half g_whi [B * NPAD];           // padding [2000,2048) stays 0
__device__ __half g_wlo [B * NPAD];

__device__ __forceinline__ uint32_t smem_u32(const void* p) {
    uint32_t a;
    asm("{ .reg .u64 t; cvta.to.shared.u64 t, %1; cvt.u32.u64 %0, t; }" : "=r"(a) : "l"(p));
    return a;
}
__device__ __forceinline__ void ldm4(uint32_t& r0, uint32_t& r1, uint32_t& r2, uint32_t& r3, uint32_t a) {
    asm volatile("ldmatrix.sync.aligned.m8n8.x4.shared.b16 {%0,%1,%2,%3}, [%4];"
                 : "=r"(r0), "=r"(r1), "=r"(r2), "=r"(r3) : "r"(a));
}
__device__ __forceinline__ void ldm4t(uint32_t& r0, uint32_t& r1, uint32_t& r2, uint32_t& r3, uint32_t a) {
    asm volatile("ldmatrix.sync.aligned.m8n8.x4.trans.shared.b16 {%0,%1,%2,%3}, [%4];"
                 : "=r"(r0), "=r"(r1), "=r"(r2), "=r"(r3) : "r"(a));
}
__device__ __forceinline__ void mma_h(float* c, uint32_t a0, uint32_t a1, uint32_t a2, uint32_t a3,
                                      uint32_t b0, uint32_t b1) {
    asm volatile("mma.sync.aligned.m16n8k16.row.col.f32.f16.f16.f32 "
                 "{%0,%1,%2,%3}, {%4,%5,%6,%7}, {%8,%9}, {%0,%1,%2,%3};"
                 : "+f"(c[0]), "+f"(c[1]), "+f"(c[2]), "+f"(c[3])
                 : "r"(a0), "r"(a1), "r"(a2), "r"(a3), "r"(b0), "r"(b1));
}
__device__ __forceinline__ uint32_t h2(float a, float b) {
    __half2 h = __floats2half2_rn(a, b);
    return *(uint32_t*)&h;
}

// ---------------------------------------------------------------------------
// Kernel 0: prepack key -> dots B fragments. Grid 196 x 256. (R7 verbatim)
// ---------------------------------------------------------------------------
__global__ __launch_bounds__(256) void prepack_kernel(const float* __restrict__ key)
{
    const int gid = blockIdx.x * 256 + threadIdx.x;
    const int t = gid & 31, s = gid >> 5;
    const int d = (s >> 2) * 64 + (s & 3) * 16 + 2 * (t & 3);
    uint32_t v0[4], v1[4];
    #pragma unroll
    for (int nf = 0; nf < 4; nf++) {
        const int row = (t >> 2) + 8 * nf;
        const float2 x0 = *(const float2*)&key[row * D + d];
        const float2 x1 = *(const float2*)&key[row * D + d + 8];
        v0[nf] = h2(x0.x, x0.y);
        v1[nf] = h2(x1.x, x1.y);
    }
    g_kb[(s * 32 + t) * 2    ] = make_uint4(v0[0], v0[1], v0[2], v0[3]);
    g_kb[(s * 32 + t) * 2 + 1] = make_uint4(v1[0], v1[1], v1[2], v1[3]);
}

// ---------------------------------------------------------------------------
// Kernel 1: dots^T partials + m-norm partials. R7 structure, ONE change:
// register pipeline deepened 2 -> 4 stages (nst always divisible by 4, so
// #pragma unroll 4 makes all stage indices compile-time constants).
// ---------------------------------------------------------------------------
__global__ __launch_bounds__(256) void dots_kernel(const float* __restrict__ mem)
{
    const int tid = threadIdx.x, w = tid >> 5, t = tid & 31;
    const int n0 = blockIdx.x * 128, kc = blockIdx.y;
    const int it0 = kc * ITOT / KC, it1 = (kc + 1) * ITOT / KC;
    const int nst = (it1 - it0) * 4;          // divisible by 4
    const int r0 = n0 + w * 16 + (t >> 2);
    const int qc = 2 * (t & 3);
    const bool ok0 = r0 < N, ok1 = (r0 + 8) < N;
    const float* q0 = mem + (long long)(ok0 ? r0 : 0) * D + it0 * 64 + qc;
    const float* q1 = mem + (long long)(ok1 ? r0 + 8 : 0) * D + it0 * 64 + qc;
    const uint4* kb = g_kb + ((long long)(it0 * 4) * 32 + t) * 2;

    float acc[4][4];
    #pragma unroll
    for (int f = 0; f < 4; f++)
        #pragma unroll
        for (int i = 0; i < 4; i++) acc[f][i] = 0.f;
    float ms0 = 0.f, ms1 = 0.f;

    float2 fa[4][4]; uint4 fb[4][2];
    // prologue: preload steps 0,1,2
    #pragma unroll
    for (int s = 0; s < 3; s++) {
        const float* a0 = q0 + s * 16;
        const float* a1 = q1 + s * 16;
        fa[s][0] = *(const float2*)a0;
        fa[s][1] = *(const float2*)a1;
        fa[s][2] = *(const float2*)(a0 + 8);
        fa[s][3] = *(const float2*)(a1 + 8);
        fb[s][0] = kb[s * 64];
        fb[s][1] = kb[s * 64 + 1];
    }

    #pragma unroll 4
    for (int j = 0; j < nst; ++j) {
        const int cur = j & 3;
        const int nxt = (j + 3) & 3;
        if (j + 3 < nst) {
            const float* a0 = q0 + (j + 3) * 16;
            const float* a1 = q1 + (j + 3) * 16;
            fa[nxt][0] = *(const float2*)a0;
            fa[nxt][1] = *(const float2*)a1;
            fa[nxt][2] = *(const float2*)(a0 + 8);
            fa[nxt][3] = *(const float2*)(a1 + 8);
            fb[nxt][0] = kb[(j + 3) * 64];
            fb[nxt][1] = kb[(j + 3) * 64 + 1];
        }
        float2 f0 = fa[cur][0], f1 = fa[cur][1], f2v = fa[cur][2], f3 = fa[cur][3];
        if (!ok0) { f0 = make_float2(0.f, 0.f); f2v = make_float2(0.f, 0.f); }
        if (!ok1) { f1 = make_float2(0.f, 0.f); f3 = make_float2(0.f, 0.f); }
        ms0 = fmaf(f0.x, f0.x, fmaf(f0.y, f0.y, ms0));
        ms0 = fmaf(f2v.x, f2v.x, fmaf(f2v.y, f2v.y, ms0));
        ms1 = fmaf(f1.x, f1.x, fmaf(f1.y, f1.y, ms1));
        ms1 = fmaf(f3.x, f3.x, fmaf(f3.y, f3.y, ms1));
        const uint32_t a0 = h2(f0.x, f0.y), a1 = h2(f1.x, f1.y);
        const uint32_t a2 = h2(f2v.x, f2v.y), a3 = h2(f3.x, f3.y);
        const uint4 B0 = fb[cur][0], B1 = fb[cur][1];
        mma_h(acc[0], a0, a1, a2, a3, B0.x, B1.x);
        mma_h(acc[1], a0, a1, a2, a3, B0.y, B1.y);
        mma_h(acc[2], a0, a1, a2, a3, B0.z, B1.z);
        mma_h(acc[3], a0, a1, a2, a3, B0.w, B1.w);
    }

    const int nrow = n0 + w * 16 + (t >> 2);
    #pragma unroll
    for (int nf = 0; nf < 4; nf++) {
        g_part[(kc * B + 8 * nf + qc    ) * NPAD + nrow    ] = acc[nf][0];
        g_part[(kc * B + 8 * nf + qc + 1) * NPAD + nrow    ] = acc[nf][1];
        g_part[(kc * B + 8 * nf + qc    ) * NPAD + nrow + 8] = acc[nf][2];
        g_part[(kc * B + 8 * nf + qc + 1) * NPAD + nrow + 8] = acc[nf][3];
    }
    ms0 += __shfl_xor_sync(0xffffffffu, ms0, 1);
    ms0 += __shfl_xor_sync(0xffffffffu, ms0, 2);
    ms1 += __shfl_xor_sync(0xffffffffu, ms1, 1);
    ms1 += __shfl_xor_sync(0xffffffffu, ms1, 2);
    if ((t & 3) == 0) {
        g_msq[kc * NPAD + n0 + w * 16 + (t >> 2)    ] = ms0;
        g_msq[kc * NPAD + n0 + w * 16 + (t >> 2) + 8] = ms1;
    }
}

// ---------------------------------------------------------------------------
// Kernel 2: norms + reduce partials + tan + softmax -> w split hi/lo fp16
// (R7 verbatim, proven)
// ---------------------------------------------------------------------------
__global__ __launch_bounds__(256) void softmax_kernel(const float* __restrict__ key)
{
    const int b = blockIdx.x, tid = threadIdx.x;
    __shared__ float red[256];
    float s = 0.f;
    for (int i = tid; i < D; i += 256) { const float v = key[b * D + i]; s = fmaf(v, v, s); }
    red[tid] = s; __syncthreads();
    for (int o = 128; o > 0; o >>= 1) { if (tid < o) red[tid] += red[tid + o]; __syncthreads(); }
    const float knorm = fmaxf(sqrtf(red[0]), EPS);
    __syncthreads();

    float sv[8], lmax = -CUDART_INF_F;
    #pragma unroll
    for (int j = 0; j < 8; j++) {
        const int n = tid + 256 * j;
        if (n < N) {
            float dot = 0.f, ms = 0.f;
            #pragma unroll
            for (int c = 0; c < KC; c++) {
                dot += g_part[(c * B + b) * NPAD + n];
                ms  += g_msq[c * NPAD + n];
            }
            const float mn = fmaxf(sqrtf(ms), EPS);
            sv[j] = tanf((dot / (knorm * mn)) * PI_2C);
            lmax = fmaxf(lmax, sv[j]);
        } else sv[j] = -CUDART_INF_F;
    }
    red[tid] = lmax; __syncthreads();
    for (int o = 128; o > 0; o >>= 1) { if (tid < o) red[tid] = fmaxf(red[tid], red[tid+o]); __syncthreads(); }
    const float mx = red[0];
    __syncthreads();

    float ev[8], ls = 0.f;
    #pragma unroll
    for (int j = 0; j < 8; j++) {
        const int n = tid + 256 * j;
        ev[j] = (n < N) ? expf(sv[j] - mx) : 0.f;
        ls += ev[j];
    }
    red[tid] = ls; __syncthreads();
    for (int o = 128; o > 0; o >>= 1) { if (tid < o) red[tid] += red[tid + o]; __syncthreads(); }
    const float inv = 1.f / red[0];
    #pragma unroll
    for (int j = 0; j < 8; j++) {
        const int n = tid + 256 * j;
        if (n < N) {
            const float wv = ev[j] * inv;
            const __half hi = __float2half(wv);
            g_whi[b * NPAD + n] = hi;
            g_wlo[b * NPAD + n] = __float2half(wv - __half2float(hi));
        }
    }
}

// ---------------------------------------------------------------------------
// Kernel 3: out[b,d] = sum_n w[b,n] m[n,d]. (R7 verbatim, proven 45.6us)
// ---------------------------------------------------------------------------
__global__ __launch_bounds__(256) void read_kernel(
    const float* __restrict__ mem, float* __restrict__ out)
{
    extern __shared__ __align__(16) char sm[];
    __half* Aw = (__half*)sm;                  // [buf][64][72]
    __half* Bt = (__half*)(sm + 18432);        // [buf][64][72]
    float*  red = (float*)sm;                  // epilogue reuse (8KB)
    const uint32_t sbA = smem_u32(Aw), sbB = smem_u32(Bt);
    const int tid = threadIdx.x, w = tid >> 5, t = tid & 31;
    const int d0 = blockIdx.x * 64;
    const int mi = w >> 2, nj = w & 3;
    const int wr = tid >> 3, ch = tid & 7;

    uint4 rAh, rAl; float4 rB[4];
    {
        rAh = *(const uint4*)&g_whi[wr * NPAD + ch * 8];
        rAl = *(const uint4*)&g_wlo[wr * NPAD + ch * 8];
        #pragma unroll
        for (int p = 0; p < 4; p++) {
            const int idx = tid + 256 * p, row = idx >> 4, c4 = idx & 15;
            rB[p] = (row < N) ? *(const float4*)&mem[(long long)row * D + d0 + c4 * 4]
                              : make_float4(0.f, 0.f, 0.f, 0.f);
        }
    }

    float acc[2][2][4];
    #pragma unroll
    for (int af = 0; af < 2; af++)
        #pragma unroll
        for (int bf = 0; bf < 2; bf++)
            #pragma unroll
            for (int i = 0; i < 4; i++) acc[af][bf][i] = 0.f;

    for (int it = 0; it < RIT; ++it) {
        const int buf = it & 1;
        __half* A  = Aw + buf * 64 * 72;
        __half* Bm = Bt + buf * 64 * 72;
        *(uint4*)&A[wr * 72 + ch * 8]        = rAh;
        *(uint4*)&A[(32 + wr) * 72 + ch * 8] = rAl;
        #pragma unroll
        for (int p = 0; p < 4; p++) {
            const int idx = tid + 256 * p, row = idx >> 4, c4 = idx & 15;
            *(uint2*)&Bm[row * 72 + c4 * 4] = make_uint2(h2(rB[p].x, rB[p].y), h2(rB[p].z, rB[p].w));
        }
        __syncthreads();
        if (it + 1 < RIT) {
            const int nb = (it + 1) * 64;
            rAh = *(const uint4*)&g_whi[wr * NPAD + nb + ch * 8];
            rAl = *(const uint4*)&g_wlo[wr * NPAD + nb + ch * 8];
            #pragma unroll
            for (int p = 0; p < 4; p++) {
                const int idx = tid + 256 * p, row = idx >> 4, c4 = idx & 15;
                const int n = nb + row;
                rB[p] = (n < N) ? *(const float4*)&mem[(long long)n * D + d0 + c4 * 4]
                                : make_float4(0.f, 0.f, 0.f, 0.f);
            }
        }
        const int lr = (t & 7) + 8 * ((t >> 3) & 1);
        const int lh = 8 * (t >> 4);
        #pragma unroll
        for (int kk = 0; kk < 4; kk++) {
            uint32_t a[2][4], bq[4];
            #pragma unroll
            for (int af = 0; af < 2; af++) {
                const uint32_t addr = sbA + 2u * (buf * 64 * 72 + (mi * 32 + af * 16 + lr) * 72 + kk * 16 + lh);
                ldm4(a[af][0], a[af][1], a[af][2], a[af][3], addr);
            }
            {
                const uint32_t addr = sbB + 2u * (buf * 64 * 72 + (kk * 16 + lr) * 72 + nj * 16 + lh);
                ldm4t(bq[0], bq[1], bq[2], bq[3], addr);
            }
            #pragma unroll
            for (int af = 0; af < 2; af++) {
                mma_h(acc[af][0], a[af][0], a[af][1], a[af][2], a[af][3], bq[0], bq[1]);
                mma_h(acc[af][1], a[af][0], a[af][1], a[af][2], a[af][3], bq[2], bq[3]);
            }
        }
        __syncthreads();
    }

    if (mi == 1) {
        #pragma unroll
        for (int af = 0; af < 2; af++)
            #pragma unroll
            for (int bf = 0; bf < 2; bf++)
                #pragma unroll
                for (int i = 0; i < 4; i++)
                    red[(nj * 32 + t) * 16 + af * 8 + bf * 4 + i] = acc[af][bf][i];
    }
    __syncthreads();
    if (mi == 0) {
        #pragma unroll
        for (int af = 0; af < 2; af++)
            #pragma unroll
            for (int bf = 0; bf < 2; bf++) {
                const float c0 = acc[af][bf][0] + red[(nj * 32 + t) * 16 + af * 8 + bf * 4 + 0];
                const float c1 = acc[af][bf][1] + red[(nj * 32 + t) * 16 + af * 8 + bf * 4 + 1];
                const float c2 = acc[af][bf][2] + red[(nj * 32 + t) * 16 + af * 8 + bf * 4 + 2];
                const float c3 = acc[af][bf][3] + red[(nj * 32 + t) * 16 + af * 8 + bf * 4 + 3];
                const int b   = af * 16 + (t >> 2);
                const int col = d0 + nj * 16 + bf * 8 + 2 * (t & 3);
                *(float2*)&out[b * D + col]       = make_float2(c0, c1);
                *(float2*)&out[(b + 8) * D + col] = make_float2(c2, c3);
            }
    }
}

// ---------------------------------------------------------------------------
extern "C" void kernel_launch(void* const* d_in, const int* in_sizes, int n_in,
                              void* d_out, int out_size)
{
    const float* key = (const float*)d_in[0];
    const float* mem = (const float*)d_in[1];
    float* out = (float*)d_out;

    cudaFuncSetAttribute(read_kernel, cudaFuncAttributeMaxDynamicSharedMemorySize, 36864);

    prepack_kernel<<<ITOT * 4 * 32 / 256, 256>>>(key);
    dots_kernel<<<dim3(16, KC), 256>>>(mem);
    softmax_kernel<<<32, 256>>>(key);
    read_kernel<<<D / 64, 256, 36864>>>(mem, out);
}